// round 9
// baseline (speedup 1.0000x reference)
#include <cuda_runtime.h>
#include <cuda_bf16.h>
#include <mma.h>
#include <cstdint>

using namespace nvcuda;

#define SD 512
#define NB 512
#define SCALE 0.044194173824159216f

// k1 (R6 shape)
#define BM 128
#define BN 128
#define BK1 32
#define LDA1 40     // bf16 stride, 128x32 tiles (80B rows)
#define LDC 132     // fp32 staging stride
#define K1_SMEM (BM * LDC * 4)   // 67584

// k2 (cp.async pipeline)
#define BK2 64
#define LDA2 72     // E tile stride (144B rows)
#define LDB2 136    // V' tile stride (272B rows)
#define K2_SMEM 71680   // A:2x18432 @0, B:2x17408 @36864

// ---- scratch (device globals; no allocation) ----
__device__ __align__(16) __nv_bfloat16 g_E[(size_t)NB * SD * SD];
__device__ __align__(16) __nv_bfloat16 g_Vh[(size_t)NB * SD * SD];
__device__ float g_partZ[NB][4][SD];
__device__ float g_Zinv[NB][SD];

__device__ __forceinline__ uint2 pack4(float4 v) {
    __nv_bfloat162 a = __float22bfloat162_rn(make_float2(v.x, v.y));
    __nv_bfloat162 b = __float22bfloat162_rn(make_float2(v.z, v.w));
    uint2 u; u.x = *(uint32_t*)&a; u.y = *(uint32_t*)&b; return u;
}
__device__ __forceinline__ uint4 pack8(float4 a, float4 b) {
    uint2 lo = pack4(a), hi = pack4(b);
    uint4 u; u.x = lo.x; u.y = lo.y; u.z = hi.x; u.w = hi.y; return u;
}
__device__ __forceinline__ uint32_t smem_u32(const void* p) {
    uint32_t a;
    asm("{ .reg .u64 t; cvta.to.shared.u64 t, %1; cvt.u32.u64 %0, t; }" : "=r"(a) : "l"(p));
    return a;
}
__device__ __forceinline__ void cpa16(uint32_t dst, const void* src) {
    asm volatile("cp.async.cg.shared.global [%0], [%1], 16;" :: "r"(dst), "l"(src));
}
#define CP_COMMIT() asm volatile("cp.async.commit_group;" ::: "memory")
#define CP_WAIT1()  asm volatile("cp.async.wait_group 1;" ::: "memory")
#define CP_WAIT0()  asm volatile("cp.async.wait_group 0;" ::: "memory")

// ---------------------------------------------------------------------------
// k1: S = Q K^T (bf16 HMMA, fp32 acc); exp in regs; E -> gmem; col partials.
// R6 version, verbatim structure (known good, 754us).
// ---------------------------------------------------------------------------
__global__ void __launch_bounds__(256, 2) k1_qk(const float* __restrict__ Q,
                                                const float* __restrict__ Km)
{
    extern __shared__ char smem_raw[];
    __nv_bfloat16* As = (__nv_bfloat16*)smem_raw;
    __nv_bfloat16* Bs = As + BM * LDA1;
    float* Cs = (float*)smem_raw;

    const int batch = blockIdx.y;
    const int it = blockIdx.x >> 2;
    const int nt = blockIdx.x & 3;
    const float* Qb = Q  + ((size_t)batch * SD + it * BM) * SD;
    const float* Kb = Km + ((size_t)batch * SD + nt * BN) * SD;

    const int tid = threadIdx.x;
    const int wid = tid >> 5;
    const int wr = wid & 3;
    const int wc = wid >> 2;

    wmma::fragment<wmma::accumulator, 16, 16, 16, float> acc[2][4];
#pragma unroll
    for (int a = 0; a < 2; a++)
#pragma unroll
        for (int b = 0; b < 4; b++) wmma::fill_fragment(acc[a][b], 0.0f);

    const int lr = tid >> 3;
    const int lc = (tid & 7) << 2;

#pragma unroll 1
    for (int kk = 0; kk < SD; kk += BK1) {
#pragma unroll
        for (int i = 0; i < 4; i++) {
            const int row = lr + (i << 5);
            float4 qa = *(const float4*)(Qb + (size_t)row * SD + kk + lc);
            float4 ka = *(const float4*)(Kb + (size_t)row * SD + kk + lc);
            *(uint2*)(As + row * LDA1 + lc) = pack4(qa);
            *(uint2*)(Bs + row * LDA1 + lc) = pack4(ka);
        }
        __syncthreads();
#pragma unroll
        for (int ks = 0; ks < BK1; ks += 16) {
            wmma::fragment<wmma::matrix_a, 16, 16, 16, __nv_bfloat16, wmma::row_major> af[2];
            wmma::fragment<wmma::matrix_b, 16, 16, 16, __nv_bfloat16, wmma::col_major> bf[4];
#pragma unroll
            for (int a = 0; a < 2; a++)
                wmma::load_matrix_sync(af[a], As + (wr * 32 + a * 16) * LDA1 + ks, LDA1);
#pragma unroll
            for (int b = 0; b < 4; b++)
                wmma::load_matrix_sync(bf[b], Bs + (wc * 64 + b * 16) * LDA1 + ks, LDA1);
#pragma unroll
            for (int a = 0; a < 2; a++)
#pragma unroll
                for (int b = 0; b < 4; b++)
                    wmma::mma_sync(acc[a][b], af[a], bf[b], acc[a][b]);
        }
        __syncthreads();
    }

#pragma unroll
    for (int a = 0; a < 2; a++)
#pragma unroll
        for (int b = 0; b < 4; b++)
#pragma unroll
            for (int e = 0; e < acc[a][b].num_elements; e++)
                acc[a][b].x[e] = __expf(acc[a][b].x[e] * SCALE);

#pragma unroll
    for (int a = 0; a < 2; a++)
#pragma unroll
        for (int b = 0; b < 4; b++)
            wmma::store_matrix_sync(Cs + (wr * 32 + a * 16) * LDC + wc * 64 + b * 16,
                                    acc[a][b], LDC, wmma::mem_row_major);
    __syncthreads();

    {
        const int col = tid & 127, half = tid >> 7;
        float zsum = 0.f;
#pragma unroll 8
        for (int r = half * 64; r < half * 64 + 64; r++)
            zsum += Cs[r * LDC + col];
        __shared__ float zs[256];
        zs[half * 128 + col] = zsum;
        __syncthreads();
        if (tid < 128)
            g_partZ[batch][it][nt * BN + tid] = zs[tid] + zs[128 + tid];
    }

    __nv_bfloat16* Eb = g_E + ((size_t)batch * SD + it * BM) * SD + nt * BN;
    {
        const int row = tid >> 1, c0 = (tid & 1) * 64;
        const float* src = Cs + row * LDC + c0;
#pragma unroll
        for (int i = 0; i < 8; i++)
            *(uint4*)(Eb + (size_t)row * SD + c0 + i * 8) =
                pack8(*(const float4*)(src + i * 8), *(const float4*)(src + i * 8 + 4));
    }
}

// ---------------------------------------------------------------------------
// k_zred: Z = fixed-order sum of 4 partials; 1/Z
// ---------------------------------------------------------------------------
__global__ void __launch_bounds__(512) k_zred()
{
    const int b = blockIdx.x, c = threadIdx.x;
    float z = g_partZ[b][0][c] + g_partZ[b][1][c] + g_partZ[b][2][c] + g_partZ[b][3][c];
    g_Zinv[b][c] = 1.0f / z;
}

// ---------------------------------------------------------------------------
// kvs: V' = V * zinv[k] -> bf16 (8 elems/thread)
// ---------------------------------------------------------------------------
__global__ void __launch_bounds__(256) kvs(const float* __restrict__ V)
{
    const int i = blockIdx.x * blockDim.x + threadIdx.x;   // chunk id
    const int b = i >> 15;            // 32768 chunks per batch (512*512/8)
    const int k = (i & 32767) >> 6;   // 64 chunks per 512-elem row
    const float zi = g_Zinv[b][k];
    const float4* src = (const float4*)(V + (size_t)i * 8);
    float4 a = src[0], c4 = src[1];
    a.x *= zi; a.y *= zi; a.z *= zi; a.w *= zi;
    c4.x *= zi; c4.y *= zi; c4.z *= zi; c4.w *= zi;
    *(uint4*)(g_Vh + (size_t)i * 8) = pack8(a, c4);
}

// ---------------------------------------------------------------------------
// k2: out = E @ V' (bf16, cp.async double-buffered, BK=64). Direct gmem store.
// 256 threads, 8 warps (4x2), warp tile 32x64. grid (16,512).
// smem: A bufs @0,@18432 (128 rows x 144B); B bufs @36864,@54272 (64 x 272B).
// ---------------------------------------------------------------------------
__global__ void __launch_bounds__(256, 2) k2_pv(float* __restrict__ O)
{
    extern __shared__ char sm[];
    const uint32_t sbase = smem_u32(sm);

    const int batch = blockIdx.y, it = blockIdx.x >> 2, jt = blockIdx.x & 3;
    const char* Eblk = (const char*)(g_E + ((size_t)batch * SD + it * 128) * SD);
    const char* Vblk = (const char*)(g_Vh + (size_t)batch * SD * SD + jt * 128);

    const int t = threadIdx.x, wid = t >> 5;
    const int wr = wid & 3, wc = wid >> 2;

    // per-thread fixed chunk coords
    const int ar = t >> 1, ac = t & 1;    // A: 128 rows x 8 chunks; 2 chunks/thread at ac*4..
    const int br = t >> 2, bc = t & 3;    // B: 64 rows x 16 chunks; 4 chunks/thread

    wmma::fragment<wmma::accumulator, 16, 16, 16, float> acc[2][4];
#pragma unroll
    for (int a = 0; a < 2; a++)
#pragma unroll
        for (int b = 0; b < 4; b++) wmma::fill_fragment(acc[a][b], 0.0f);

#pragma unroll 1
    for (int pre = 0; pre < 2; pre++) {
        const uint32_t abuf = sbase + pre * 18432;
        const uint32_t bbuf = sbase + 36864 + pre * 17408;
        const int kk = pre * BK2;
        // A: thread t covers (row=ar, chunks ac*4 .. ac*4+3)
#pragma unroll
        for (int q = 0; q < 4; q++)
            cpa16(abuf + (uint32_t)(ar * 144 + (ac * 4 + q) * 16),
                  Eblk + (size_t)ar * 1024 + (size_t)kk * 2 + (ac * 4 + q) * 16);
        // B: thread t covers (row=br, chunks bc*4 .. bc*4+3)
#pragma unroll
        for (int q = 0; q < 4; q++)
            cpa16(bbuf + (uint32_t)(br * 272 + (bc * 4 + q) * 16),
                  Vblk + (size_t)(kk + br) * 1024 + (bc * 4 + q) * 16);
        CP_COMMIT();
    }

#pragma unroll 1
    for (int c = 0; c < 8; c++) {
        if (c < 6) CP_WAIT1(); else CP_WAIT0();
        __syncthreads();
        const int buf = c & 1;
        const __nv_bfloat16* As = (const __nv_bfloat16*)(sm + buf * 18432);
        const __nv_bfloat16* Bs = (const __nv_bfloat16*)(sm + 36864 + buf * 17408);
#pragma unroll
        for (int ks = 0; ks < BK2; ks += 16) {
            wmma::fragment<wmma::matrix_a, 16, 16, 16, __nv_bfloat16, wmma::row_major> af[2];
            wmma::fragment<wmma::matrix_b, 16, 16, 16, __nv_bfloat16, wmma::row_major> bf[4];
#pragma unroll
            for (int a = 0; a < 2; a++)
                wmma::load_matrix_sync(af[a], As + (wr * 32 + a * 16) * LDA2 + ks, LDA2);
#pragma unroll
            for (int b = 0; b < 4; b++)
                wmma::load_matrix_sync(bf[b], Bs + ks * LDB2 + wc * 64 + b * 16, LDB2);
#pragma unroll
            for (int a = 0; a < 2; a++)
#pragma unroll
                for (int b = 0; b < 4; b++)
                    wmma::mma_sync(acc[a][b], af[a], bf[b], acc[a][b]);
        }
        __syncthreads();
        if (c < 6) {
            const uint32_t abuf = sbase + buf * 18432;
            const uint32_t bbuf = sbase + 36864 + buf * 17408;
            const int kk = (c + 2) * BK2;
#pragma unroll
            for (int q = 0; q < 4; q++)
                cpa16(abuf + (uint32_t)(ar * 144 + (ac * 4 + q) * 16),
                      Eblk + (size_t)ar * 1024 + (size_t)kk * 2 + (ac * 4 + q) * 16);
#pragma unroll
            for (int q = 0; q < 4; q++)
                cpa16(bbuf + (uint32_t)(br * 272 + (bc * 4 + q) * 16),
                      Vblk + (size_t)(kk + br) * 1024 + (bc * 4 + q) * 16);
            CP_COMMIT();
        }
    }

    float* Ob = O + ((size_t)batch * SD + it * 128) * SD + jt * 128;
#pragma unroll
    for (int a = 0; a < 2; a++)
#pragma unroll
        for (int b = 0; b < 4; b++)
            wmma::store_matrix_sync(Ob + (size_t)(wr * 32 + a * 16) * SD + wc * 64 + b * 16,
                                    acc[a][b], SD, wmma::mem_row_major);
}

// ---------------------------------------------------------------------------
extern "C" void kernel_launch(void* const* d_in, const int* in_sizes, int n_in,
                              void* d_out, int out_size)
{
    (void)in_sizes; (void)n_in; (void)out_size;
    const float* Q = (const float*)d_in[1];
    const float* K = (const float*)d_in[2];
    const float* V = (const float*)d_in[3];
    float* out = (float*)d_out;

    cudaFuncSetAttribute(k1_qk, cudaFuncAttributeMaxDynamicSharedMemorySize, K1_SMEM);
    cudaFuncSetAttribute(k2_pv, cudaFuncAttributeMaxDynamicSharedMemorySize, K2_SMEM);

    const int nchunk = (int)((size_t)NB * SD * SD / 8);   // 16777216
    dim3 g(16, NB);
    k1_qk<<<g, 256, K1_SMEM>>>(Q, K);
    k_zred<<<NB, 512>>>();
    kvs<<<nchunk / 256, 256>>>(V);
    k2_pv<<<g, 256, K2_SMEM>>>(out);
}

// round 10
// speedup vs baseline: 1.1377x; 1.1377x over previous
#include <cuda_runtime.h>
#include <cuda_bf16.h>
#include <cstdint>

#define SD 512
#define NB 512
#define SCALE 0.044194173824159216f

#define LDC 132        // fp32 staging stride (floats)
#define LDE 144        // byte stride: bf16 tile rows (72 bf16)
#define LDV 272        // byte stride: k2 B tile rows (136 bf16)
#define K1_SMEM 67584  // As@0 (18432), Bs@18432 (18432); Cs fp32 aliases (67584)
#define K2_SMEM 71680  // A bufs @0,@18432; B bufs @36864,@54272 (17408 each)

// ---- scratch (device globals; no allocation) ----
__device__ __align__(16) __nv_bfloat16 g_E[(size_t)NB * SD * SD];
__device__ __align__(16) __nv_bfloat16 g_Vh[(size_t)NB * SD * SD];
__device__ float g_partZ[NB][4][SD];
__device__ float g_Zinv[NB][SD];

__device__ __forceinline__ uint2 pack4(float4 v) {
    __nv_bfloat162 a = __float22bfloat162_rn(make_float2(v.x, v.y));
    __nv_bfloat162 b = __float22bfloat162_rn(make_float2(v.z, v.w));
    uint2 u; u.x = *(uint32_t*)&a; u.y = *(uint32_t*)&b; return u;
}
__device__ __forceinline__ uint4 pack8(float4 a, float4 b) {
    uint2 lo = pack4(a), hi = pack4(b);
    uint4 u; u.x = lo.x; u.y = lo.y; u.z = hi.x; u.w = hi.y; return u;
}
__device__ __forceinline__ uint32_t smem_u32(const void* p) {
    uint32_t a;
    asm("{ .reg .u64 t; cvta.to.shared.u64 t, %1; cvt.u32.u64 %0, t; }" : "=r"(a) : "l"(p));
    return a;
}
__device__ __forceinline__ void cpa16(uint32_t dst, const void* src) {
    asm volatile("cp.async.cg.shared.global [%0], [%1], 16;" :: "r"(dst), "l"(src));
}
#define CP_COMMIT() asm volatile("cp.async.commit_group;" ::: "memory")
#define CP_WAIT1()  asm volatile("cp.async.wait_group 1;" ::: "memory")
#define CP_WAIT0()  asm volatile("cp.async.wait_group 0;" ::: "memory")

__device__ __forceinline__ void ldsm4(uint32_t* r, uint32_t a) {
    asm volatile("ldmatrix.sync.aligned.m8n8.x4.shared.b16 {%0,%1,%2,%3}, [%4];"
                 : "=r"(r[0]), "=r"(r[1]), "=r"(r[2]), "=r"(r[3]) : "r"(a));
}
__device__ __forceinline__ void ldsm4t(uint32_t* r, uint32_t a) {
    asm volatile("ldmatrix.sync.aligned.m8n8.x4.trans.shared.b16 {%0,%1,%2,%3}, [%4];"
                 : "=r"(r[0]), "=r"(r[1]), "=r"(r[2]), "=r"(r[3]) : "r"(a));
}
__device__ __forceinline__ void mma16816(float* d, const uint32_t* a, const uint32_t* b) {
    asm volatile(
        "mma.sync.aligned.m16n8k16.row.col.f32.bf16.bf16.f32 "
        "{%0,%1,%2,%3},{%4,%5,%6,%7},{%8,%9},{%0,%1,%2,%3};"
        : "+f"(d[0]), "+f"(d[1]), "+f"(d[2]), "+f"(d[3])
        : "r"(a[0]), "r"(a[1]), "r"(a[2]), "r"(a[3]), "r"(b[0]), "r"(b[1]));
}

// ---------------------------------------------------------------------------
// k1: S = Q K^T (raw mma, fp32 acc); exp in regs; E -> gmem; col partials.
// 256 thr, 8 warps (4 row x 2 col), warp tile 32x64, CTA 128x128, BK=64.
// smem: As@0 [128 rows x 144B], Bs@18432 same; Cs fp32 [128][132] aliases.
// ---------------------------------------------------------------------------
__global__ void __launch_bounds__(256, 2) k1_qk(const float* __restrict__ Q,
                                                const float* __restrict__ Km)
{
    extern __shared__ char sm[];
    const uint32_t sb = smem_u32(sm);
    __shared__ float zsh[256];

    const int batch = blockIdx.y, it = blockIdx.x >> 2, nt = blockIdx.x & 3;
    const float* Qb = Q  + ((size_t)batch * SD + it * 128) * SD;
    const float* Kb = Km + ((size_t)batch * SD + nt * 128) * SD;

    const int t = threadIdx.x, lane = t & 31, wid = t >> 5;
    const int R = (wid & 3) * 32, C = (wid >> 2) * 64;

    float d[2][8][4];
#pragma unroll
    for (int i = 0; i < 2; i++)
#pragma unroll
        for (int j = 0; j < 8; j++)
#pragma unroll
            for (int e = 0; e < 4; e++) d[i][j][e] = 0.0f;

    // fill indices
    const int lr = t >> 3, lc8 = (t & 7) * 8;
    // ldmatrix per-lane byte offsets (A: bit3->row+8, bit4->k+16; B: swapped)
    const int aRow = (lane & 7) + ((lane >> 3) & 1) * 8;
    const uint32_t aK = ((lane >> 4) & 1) * 16;
    const uint32_t aBase = sb + (uint32_t)(R + aRow) * LDE + aK;
    const int bRow = (lane & 7) + ((lane >> 4) & 1) * 8;
    const uint32_t bK = ((lane >> 3) & 1) * 16;
    const uint32_t bBase = sb + 18432u + (uint32_t)(C + bRow) * LDE + bK;

#pragma unroll 1
    for (int ch = 0; ch < 8; ch++) {
        const int kk = ch * 64;
        // fill As (Q) and Bs (K): 128 rows x 64 bf16 each, fp32->bf16 pack
#pragma unroll
        for (int p = 0; p < 4; p++) {
            const int row = lr + p * 32;
            const float* qp = Qb + (size_t)row * SD + kk + lc8;
            const float* kp = Kb + (size_t)row * SD + kk + lc8;
            *(uint4*)(sm + row * LDE + lc8 * 2) =
                pack8(*(const float4*)qp, *(const float4*)(qp + 4));
            *(uint4*)(sm + 18432 + row * LDE + lc8 * 2) =
                pack8(*(const float4*)kp, *(const float4*)(kp + 4));
        }
        __syncthreads();

        uint32_t afr[2][2][4], bfr[2][4][4];
        // preload ks=0 fragments
#pragma unroll
        for (int i = 0; i < 2; i++) ldsm4(afr[0][i], aBase + i * 16 * LDE);
#pragma unroll
        for (int j = 0; j < 4; j++) ldsm4(bfr[0][j], bBase + j * 16 * LDE);

#pragma unroll
        for (int ks = 0; ks < 4; ks++) {
            const int cur = ks & 1, nxt = cur ^ 1;
            if (ks < 3) {
                const uint32_t ko = (uint32_t)(ks + 1) * 32;
#pragma unroll
                for (int i = 0; i < 2; i++) ldsm4(afr[nxt][i], aBase + i * 16 * LDE + ko);
#pragma unroll
                for (int j = 0; j < 4; j++) ldsm4(bfr[nxt][j], bBase + j * 16 * LDE + ko);
            }
#pragma unroll
            for (int i = 0; i < 2; i++)
#pragma unroll
                for (int j = 0; j < 4; j++) {
                    mma16816(d[i][2 * j],     afr[cur][i], &bfr[cur][j][0]);
                    mma16816(d[i][2 * j + 1], afr[cur][i], &bfr[cur][j][2]);
                }
        }
        __syncthreads();
    }

    // exp in registers
#pragma unroll
    for (int i = 0; i < 2; i++)
#pragma unroll
        for (int j = 0; j < 8; j++)
#pragma unroll
            for (int e = 0; e < 4; e++)
                d[i][j][e] = __expf(d[i][j][e] * SCALE);

    // stage to fp32 smem (aliases tiles; all ldmatrix complete)
    float* Cs = (float*)sm;
#pragma unroll
    for (int i = 0; i < 2; i++)
#pragma unroll
        for (int j = 0; j < 8; j++) {
            const int row = R + 16 * i + (lane >> 2);
            const int col = C + 8 * j + (lane & 3) * 2;
            *(float2*)&Cs[row * LDC + col] = make_float2(d[i][j][0], d[i][j][1]);
            *(float2*)&Cs[(row + 8) * LDC + col] = make_float2(d[i][j][2], d[i][j][3]);
        }
    __syncthreads();

    // deterministic column partial sums (2 threads/col, fixed order)
    {
        const int col = t & 127, half = t >> 7;
        float zsum = 0.f;
#pragma unroll 8
        for (int r = half * 64; r < half * 64 + 64; r++)
            zsum += Cs[r * LDC + col];
        zsh[half * 128 + col] = zsum;
        __syncthreads();
        if (t < 128)
            g_partZ[batch][it][nt * 128 + t] = zsh[t] + zsh[128 + t];
    }

    // coalesced bf16 E store
    __nv_bfloat16* Eb = g_E + ((size_t)batch * SD + it * 128) * SD + nt * 128;
    {
        const int row = t >> 1, c0 = (t & 1) * 64;
        const float* src = Cs + row * LDC + c0;
#pragma unroll
        for (int i = 0; i < 8; i++)
            *(uint4*)(Eb + (size_t)row * SD + c0 + i * 8) =
                pack8(*(const float4*)(src + i * 8), *(const float4*)(src + i * 8 + 4));
    }
}

// ---------------------------------------------------------------------------
// k_zred: Z = fixed-order sum of 4 partials; 1/Z
// ---------------------------------------------------------------------------
__global__ void __launch_bounds__(512) k_zred()
{
    const int b = blockIdx.x, c = threadIdx.x;
    float z = g_partZ[b][0][c] + g_partZ[b][1][c] + g_partZ[b][2][c] + g_partZ[b][3][c];
    g_Zinv[b][c] = 1.0f / z;
}

// ---------------------------------------------------------------------------
// kvs: V' = V * zinv[k] -> bf16 (8 elems/thread)
// ---------------------------------------------------------------------------
__global__ void __launch_bounds__(256) kvs(const float* __restrict__ V)
{
    const int i = blockIdx.x * blockDim.x + threadIdx.x;
    const int b = i >> 15;
    const int k = (i & 32767) >> 6;
    const float zi = g_Zinv[b][k];
    const float4* src = (const float4*)(V + (size_t)i * 8);
    float4 a = src[0], c4 = src[1];
    a.x *= zi; a.y *= zi; a.z *= zi; a.w *= zi;
    c4.x *= zi; c4.y *= zi; c4.z *= zi; c4.w *= zi;
    *(uint4*)(g_Vh + (size_t)i * 8) = pack8(a, c4);
}

// ---------------------------------------------------------------------------
// k2: out = E @ V' (raw mma + validated cp.async pipeline, BK=64).
// A = E [row][k] bf16 (144B rows); B = V' [k][j] bf16 (272B rows), ldmatrix.trans.
// Direct float2 gmem stores.
// ---------------------------------------------------------------------------
__global__ void __launch_bounds__(256, 2) k2_pv(float* __restrict__ O)
{
    extern __shared__ char sm[];
    const uint32_t sb = smem_u32(sm);

    const int batch = blockIdx.y, it = blockIdx.x >> 2, jt = blockIdx.x & 3;
    const char* Eblk = (const char*)(g_E + ((size_t)batch * SD + it * 128) * SD);
    const char* Vblk = (const char*)(g_Vh + (size_t)batch * SD * SD + jt * 128);

    const int t = threadIdx.x, lane = t & 31, wid = t >> 5;
    const int R = (wid & 3) * 32, C = (wid >> 2) * 64;

    // cp.async fill coords (validated in R9)
    const int ar = t >> 1, ac = t & 1;
    const int br = t >> 2, bc = t & 3;

    // ldmatrix per-lane offsets
    const int aRow = (lane & 7) + ((lane >> 3) & 1) * 8;
    const uint32_t aK = ((lane >> 4) & 1) * 16;
    const uint32_t aBase = sb + (uint32_t)(R + aRow) * LDE + aK;
    const int bKrow = lane & 15;
    const uint32_t bN = ((lane >> 4) & 1) * 16;
    const uint32_t bBase = sb + 36864u + (uint32_t)bKrow * LDV + (uint32_t)C * 2 + bN;

    float d[2][8][4];
#pragma unroll
    for (int i = 0; i < 2; i++)
#pragma unroll
        for (int j = 0; j < 8; j++)
#pragma unroll
            for (int e = 0; e < 4; e++) d[i][j][e] = 0.0f;

#pragma unroll 1
    for (int pre = 0; pre < 2; pre++) {
        const uint32_t abuf = sb + pre * 18432;
        const uint32_t bbuf = sb + 36864 + pre * 17408;
        const int kk = pre * 64;
#pragma unroll
        for (int q = 0; q < 4; q++)
            cpa16(abuf + (uint32_t)(ar * 144 + (ac * 4 + q) * 16),
                  Eblk + (size_t)ar * 1024 + (size_t)kk * 2 + (ac * 4 + q) * 16);
#pragma unroll
        for (int q = 0; q < 4; q++)
            cpa16(bbuf + (uint32_t)(br * 272 + (bc * 4 + q) * 16),
                  Vblk + (size_t)(kk + br) * 1024 + (bc * 4 + q) * 16);
        CP_COMMIT();
    }

#pragma unroll 1
    for (int c = 0; c < 8; c++) {
        if (c < 6) CP_WAIT1(); else CP_WAIT0();
        __syncthreads();
        const int buf = c & 1;
        const uint32_t aB = aBase + buf * 18432u;
        const uint32_t bB = bBase + buf * 17408u;

        uint32_t afr[2][2][4], bfr[2][4][4];
#pragma unroll
        for (int i = 0; i < 2; i++) ldsm4(afr[0][i], aB + i * 16 * LDE);
#pragma unroll
        for (int j = 0; j < 4; j++) ldsm4t(bfr[0][j], bB + j * 32);

#pragma unroll
        for (int ks = 0; ks < 4; ks++) {
            const int cur = ks & 1, nxt = cur ^ 1;
            if (ks < 3) {
                const uint32_t ao = (uint32_t)(ks + 1) * 32;
                const uint32_t bo = (uint32_t)(ks + 1) * (16 * LDV);
#pragma unroll
                for (int i = 0; i < 2; i++) ldsm4(afr[nxt][i], aB + i * 16 * LDE + ao);
#pragma unroll
                for (int j = 0; j < 4; j++) ldsm4t(bfr[nxt][j], bB + j * 32 + bo);
            }
#pragma unroll
            for (int i = 0; i < 2; i++)
#pragma unroll
                for (int j = 0; j < 4; j++) {
                    mma16816(d[i][2 * j],     afr[cur][i], &bfr[cur][j][0]);
                    mma16816(d[i][2 * j + 1], afr[cur][i], &bfr[cur][j][2]);
                }
        }
        __syncthreads();

        if (c < 6) {
            const uint32_t abuf = sb + buf * 18432;
            const uint32_t bbuf = sb + 36864 + buf * 17408;
            const int kk = (c + 2) * 64;
#pragma unroll
            for (int q = 0; q < 4; q++)
                cpa16(abuf + (uint32_t)(ar * 144 + (ac * 4 + q) * 16),
                      Eblk + (size_t)ar * 1024 + (size_t)kk * 2 + (ac * 4 + q) * 16);
#pragma unroll
            for (int q = 0; q < 4; q++)
                cpa16(bbuf + (uint32_t)(br * 272 + (bc * 4 + q) * 16),
                      Vblk + (size_t)(kk + br) * 1024 + (bc * 4 + q) * 16);
            CP_COMMIT();
        }
    }

    // direct gmem stores
    float* Ob = O + ((size_t)batch * SD + it * 128) * SD + jt * 128;
#pragma unroll
    for (int i = 0; i < 2; i++)
#pragma unroll
        for (int j = 0; j < 8; j++) {
            const int row = R + 16 * i + (lane >> 2);
            const int col = C + 8 * j + (lane & 3) * 2;
            *(float2*)(Ob + (size_t)row * SD + col) = make_float2(d[i][j][0], d[i][j][1]);
            *(float2*)(Ob + (size_t)(row + 8) * SD + col) = make_float2(d[i][j][2], d[i][j][3]);
        }
}

// ---------------------------------------------------------------------------
extern "C" void kernel_launch(void* const* d_in, const int* in_sizes, int n_in,
                              void* d_out, int out_size)
{
    (void)in_sizes; (void)n_in; (void)out_size;
    const float* Q = (const float*)d_in[1];
    const float* K = (const float*)d_in[2];
    const float* V = (const float*)d_in[3];
    float* out = (float*)d_out;

    cudaFuncSetAttribute(k1_qk, cudaFuncAttributeMaxDynamicSharedMemorySize, K1_SMEM);
    cudaFuncSetAttribute(k2_pv, cudaFuncAttributeMaxDynamicSharedMemorySize, K2_SMEM);

    const int nchunk = (int)((size_t)NB * SD * SD / 8);
    dim3 g(16, NB);
    k1_qk<<<g, 256, K1_SMEM>>>(Q, K);
    k_zred<<<NB, 512>>>();
    kvs<<<nchunk / 256, 256>>>(V);
    k2_pv<<<g, 256, K2_SMEM>>>(out);
}

// round 11
// speedup vs baseline: 1.2080x; 1.0618x over previous
#include <cuda_runtime.h>
#include <cuda_bf16.h>
#include <cstdint>

#define SD 512
#define NB 512
#define SCALE 0.044194173824159216f

#define LDC 132        // fp32 staging stride (floats)
#define LDE1 80        // k1 byte stride: 32-bf16 rows (BK=32)
#define LDE 144        // k2 byte stride: 64-bf16 rows
#define LDV 272        // k2 B tile byte stride (136 bf16)
#define K1_SMEM 67584  // A0@0,A1@10240,B0@20480,B1@30720 (40960); Cs fp32 aliases
#define K2_SMEM 71680  // A bufs @0,@18432; B bufs @36864,@54272 (17408 each)

// ---- scratch (device globals; no allocation) ----
__device__ __align__(16) __nv_bfloat16 g_E[(size_t)NB * SD * SD];
__device__ __align__(16) __nv_bfloat16 g_Vh[(size_t)NB * SD * SD];
__device__ float g_partZ[NB][4][SD];
__device__ float g_Zinv[NB][SD];

__device__ __forceinline__ uint2 pack4(float4 v) {
    __nv_bfloat162 a = __float22bfloat162_rn(make_float2(v.x, v.y));
    __nv_bfloat162 b = __float22bfloat162_rn(make_float2(v.z, v.w));
    uint2 u; u.x = *(uint32_t*)&a; u.y = *(uint32_t*)&b; return u;
}
__device__ __forceinline__ uint4 pack8(float4 a, float4 b) {
    uint2 lo = pack4(a), hi = pack4(b);
    uint4 u; u.x = lo.x; u.y = lo.y; u.z = hi.x; u.w = hi.y; return u;
}
__device__ __forceinline__ uint32_t smem_u32(const void* p) {
    uint32_t a;
    asm("{ .reg .u64 t; cvta.to.shared.u64 t, %1; cvt.u32.u64 %0, t; }" : "=r"(a) : "l"(p));
    return a;
}
__device__ __forceinline__ void cpa16(uint32_t dst, const void* src) {
    asm volatile("cp.async.cg.shared.global [%0], [%1], 16;" :: "r"(dst), "l"(src));
}
#define CP_COMMIT() asm volatile("cp.async.commit_group;" ::: "memory")
#define CP_WAIT1()  asm volatile("cp.async.wait_group 1;" ::: "memory")
#define CP_WAIT0()  asm volatile("cp.async.wait_group 0;" ::: "memory")

__device__ __forceinline__ void ldsm4(uint32_t* r, uint32_t a) {
    asm volatile("ldmatrix.sync.aligned.m8n8.x4.shared.b16 {%0,%1,%2,%3}, [%4];"
                 : "=r"(r[0]), "=r"(r[1]), "=r"(r[2]), "=r"(r[3]) : "r"(a));
}
__device__ __forceinline__ void ldsm4t(uint32_t* r, uint32_t a) {
    asm volatile("ldmatrix.sync.aligned.m8n8.x4.trans.shared.b16 {%0,%1,%2,%3}, [%4];"
                 : "=r"(r[0]), "=r"(r[1]), "=r"(r[2]), "=r"(r[3]) : "r"(a));
}
__device__ __forceinline__ void mma16816(float* d, const uint32_t* a, const uint32_t* b) {
    asm volatile(
        "mma.sync.aligned.m16n8k16.row.col.f32.bf16.bf16.f32 "
        "{%0,%1,%2,%3},{%4,%5,%6,%7},{%8,%9},{%0,%1,%2,%3};"
        : "+f"(d[0]), "+f"(d[1]), "+f"(d[2]), "+f"(d[3])
        : "r"(a[0]), "r"(a[1]), "r"(a[2]), "r"(a[3]), "r"(b[0]), "r"(b[1]));
}

// ---------------------------------------------------------------------------
// k1: S = Q K^T (raw mma); register-prefetch + smem double-buffer, BK=32.
// 256 thr, 8 warps (4x2), warp tile 32x64. grid (16,512), 2 CTA/SM.
// smem: A0@0 A1@10240 B0@20480 B1@30720 (128 rows x 80B each); Cs aliases @0.
// ---------------------------------------------------------------------------
__global__ void __launch_bounds__(256, 2) k1_qk(const float* __restrict__ Q,
                                                const float* __restrict__ Km)
{
    extern __shared__ char sm[];
    const uint32_t sb = smem_u32(sm);
    __shared__ float zsh[256];

    const int batch = blockIdx.y, it = blockIdx.x >> 2, nt = blockIdx.x & 3;
    const float* Qb = Q  + ((size_t)batch * SD + it * 128) * SD;
    const float* Kb = Km + ((size_t)batch * SD + nt * 128) * SD;

    const int t = threadIdx.x, lane = t & 31, wid = t >> 5;
    const int R = (wid & 3) * 32, C = (wid >> 2) * 64;

    float d[2][8][4];
#pragma unroll
    for (int i = 0; i < 2; i++)
#pragma unroll
        for (int j = 0; j < 8; j++)
#pragma unroll
            for (int e = 0; e < 4; e++) d[i][j][e] = 0.0f;

    // fill coords: thread covers rows r0+{0,32,64,96}, float cols fc..fc+3
    const int r0 = t >> 3, fc = (t & 7) * 4;
    // ldmatrix per-lane offsets (BK=32 tiles, 80B rows)
    const int aRow = (lane & 7) + ((lane >> 3) & 1) * 8;
    const uint32_t aK = ((lane >> 4) & 1) * 16;
    const uint32_t aBase = sb + (uint32_t)(R + aRow) * LDE1 + aK;
    const int bRow = (lane & 7) + ((lane >> 4) & 1) * 8;
    const uint32_t bK = ((lane >> 3) & 1) * 16;
    const uint32_t bBase = sb + 20480u + (uint32_t)(C + bRow) * LDE1 + bK;

    float4 pq[4], pk[4];   // prefetch registers (held across compute)

    auto ldgc = [&](int kk) {
#pragma unroll
        for (int p = 0; p < 4; p++) {
            const int row = r0 + p * 32;
            pq[p] = *(const float4*)(Qb + (size_t)row * SD + kk + fc);
            pk[p] = *(const float4*)(Kb + (size_t)row * SD + kk + fc);
        }
    };
    auto stsc = [&](int buf) {
#pragma unroll
        for (int p = 0; p < 4; p++) {
            const int row = r0 + p * 32;
            *(uint2*)(sm + buf * 10240 + row * LDE1 + fc * 2) = pack4(pq[p]);
            *(uint2*)(sm + 20480 + buf * 10240 + row * LDE1 + fc * 2) = pack4(pk[p]);
        }
    };

    // prologue: chunk0 -> buf0 (LDG stall unavoidable once), prefetch chunk1
    ldgc(0);
    stsc(0);
    ldgc(32);
    __syncthreads();

#pragma unroll 1
    for (int c = 0; c < 16; c++) {
        const int buf = c & 1;
        const uint32_t aB = aBase + (uint32_t)buf * 10240u;
        const uint32_t bB = bBase + (uint32_t)buf * 10240u;
        uint32_t afr[2][4], bfr[4][4];
#pragma unroll
        for (int ks = 0; ks < 2; ks++) {
            const uint32_t ko = (uint32_t)ks * 32;
#pragma unroll
            for (int i = 0; i < 2; i++) ldsm4(afr[i], aB + i * 16 * LDE1 + ko);
#pragma unroll
            for (int j = 0; j < 4; j++) ldsm4(bfr[j], bB + j * 16 * LDE1 + ko);
#pragma unroll
            for (int i = 0; i < 2; i++)
#pragma unroll
                for (int j = 0; j < 4; j++) {
                    mma16816(d[i][2 * j],     afr[i], &bfr[j][0]);
                    mma16816(d[i][2 * j + 1], afr[i], &bfr[j][2]);
                }
        }
        __syncthreads();   // all reads of buf done; safe to overwrite buf^1's partner
        if (c < 15) {
            stsc(buf ^ 1);               // chunk c+1 (prefetched regs; LDG landed)
            if (c < 14) ldgc((c + 2) * 32);
            __syncthreads();             // writes visible before next compute
        }
    }

    // exp in registers
#pragma unroll
    for (int i = 0; i < 2; i++)
#pragma unroll
        for (int j = 0; j < 8; j++)
#pragma unroll
            for (int e = 0; e < 4; e++)
                d[i][j][e] = __expf(d[i][j][e] * SCALE);

    // stage to fp32 smem (aliases tiles; all reads complete)
    float* Cs = (float*)sm;
    __syncthreads();
#pragma unroll
    for (int i = 0; i < 2; i++)
#pragma unroll
        for (int j = 0; j < 8; j++) {
            const int row = R + 16 * i + (lane >> 2);
            const int col = C + 8 * j + (lane & 3) * 2;
            *(float2*)&Cs[row * LDC + col] = make_float2(d[i][j][0], d[i][j][1]);
            *(float2*)&Cs[(row + 8) * LDC + col] = make_float2(d[i][j][2], d[i][j][3]);
        }
    __syncthreads();

    // deterministic column partial sums (2 threads/col, fixed order)
    {
        const int col = t & 127, half = t >> 7;
        float zsum = 0.f;
#pragma unroll 8
        for (int r = half * 64; r < half * 64 + 64; r++)
            zsum += Cs[r * LDC + col];
        zsh[half * 128 + col] = zsum;
        __syncthreads();
        if (t < 128)
            g_partZ[batch][it][nt * 128 + t] = zsh[t] + zsh[128 + t];
    }

    // coalesced bf16 E store
    __nv_bfloat16* Eb = g_E + ((size_t)batch * SD + it * 128) * SD + nt * 128;
    {
        const int row = t >> 1, c0 = (t & 1) * 64;
        const float* src = Cs + row * LDC + c0;
#pragma unroll
        for (int i = 0; i < 8; i++)
            *(uint4*)(Eb + (size_t)row * SD + c0 + i * 8) =
                pack8(*(const float4*)(src + i * 8), *(const float4*)(src + i * 8 + 4));
    }
}

// ---------------------------------------------------------------------------
// k_zred: Z = fixed-order sum of 4 partials; 1/Z
// ---------------------------------------------------------------------------
__global__ void __launch_bounds__(512) k_zred()
{
    const int b = blockIdx.x, c = threadIdx.x;
    float z = g_partZ[b][0][c] + g_partZ[b][1][c] + g_partZ[b][2][c] + g_partZ[b][3][c];
    g_Zinv[b][c] = 1.0f / z;
}

// ---------------------------------------------------------------------------
// kvs: V' = V * zinv[k] -> bf16 (8 elems/thread)
// ---------------------------------------------------------------------------
__global__ void __launch_bounds__(256) kvs(const float* __restrict__ V)
{
    const int i = blockIdx.x * blockDim.x + threadIdx.x;
    const int b = i >> 15;
    const int k = (i & 32767) >> 6;
    const float zi = g_Zinv[b][k];
    const float4* src = (const float4*)(V + (size_t)i * 8);
    float4 a = src[0], c4 = src[1];
    a.x *= zi; a.y *= zi; a.z *= zi; a.w *= zi;
    c4.x *= zi; c4.y *= zi; c4.z *= zi; c4.w *= zi;
    *(uint4*)(g_Vh + (size_t)i * 8) = pack8(a, c4);
}

// ---------------------------------------------------------------------------
// k2: out = E @ V' (raw mma + cp.async pipeline, BK=64). Verbatim from R10.
// ---------------------------------------------------------------------------
__global__ void __launch_bounds__(256, 2) k2_pv(float* __restrict__ O)
{
    extern __shared__ char sm[];
    const uint32_t sb = smem_u32(sm);

    const int batch = blockIdx.y, it = blockIdx.x >> 2, jt = blockIdx.x & 3;
    const char* Eblk = (const char*)(g_E + ((size_t)batch * SD + it * 128) * SD);
    const char* Vblk = (const char*)(g_Vh + (size_t)batch * SD * SD + jt * 128);

    const int t = threadIdx.x, lane = t & 31, wid = t >> 5;
    const int R = (wid & 3) * 32, C = (wid >> 2) * 64;

    const int ar = t >> 1, ac = t & 1;
    const int br = t >> 2, bc = t & 3;

    const int aRow = (lane & 7) + ((lane >> 3) & 1) * 8;
    const uint32_t aK = ((lane >> 4) & 1) * 16;
    const uint32_t aBase = sb + (uint32_t)(R + aRow) * LDE + aK;
    const int bKrow = lane & 15;
    const uint32_t bN = ((lane >> 4) & 1) * 16;
    const uint32_t bBase = sb + 36864u + (uint32_t)bKrow * LDV + (uint32_t)C * 2 + bN;

    float d[2][8][4];
#pragma unroll
    for (int i = 0; i < 2; i++)
#pragma unroll
        for (int j = 0; j < 8; j++)
#pragma unroll
            for (int e = 0; e < 4; e++) d[i][j][e] = 0.0f;

#pragma unroll 1
    for (int pre = 0; pre < 2; pre++) {
        const uint32_t abuf = sb + pre * 18432;
        const uint32_t bbuf = sb + 36864 + pre * 17408;
        const int kk = pre * 64;
#pragma unroll
        for (int q = 0; q < 4; q++)
            cpa16(abuf + (uint32_t)(ar * 144 + (ac * 4 + q) * 16),
                  Eblk + (size_t)ar * 1024 + (size_t)kk * 2 + (ac * 4 + q) * 16);
#pragma unroll
        for (int q = 0; q < 4; q++)
            cpa16(bbuf + (uint32_t)(br * 272 + (bc * 4 + q) * 16),
                  Vblk + (size_t)(kk + br) * 1024 + (bc * 4 + q) * 16);
        CP_COMMIT();
    }

#pragma unroll 1
    for (int c = 0; c < 8; c++) {
        if (c < 6) CP_WAIT1(); else CP_WAIT0();
        __syncthreads();
        const int buf = c & 1;
        const uint32_t aB = aBase + buf * 18432u;
        const uint32_t bB = bBase + buf * 17408u;

        uint32_t afr[2][2][4], bfr[2][4][4];
#pragma unroll
        for (int i = 0; i < 2; i++) ldsm4(afr[0][i], aB + i * 16 * LDE);
#pragma unroll
        for (int j = 0; j < 4; j++) ldsm4t(bfr[0][j], bB + j * 32);

#pragma unroll
        for (int ks = 0; ks < 4; ks++) {
            const int cur = ks & 1, nxt = cur ^ 1;
            if (ks < 3) {
                const uint32_t ao = (uint32_t)(ks + 1) * 32;
                const uint32_t bo = (uint32_t)(ks + 1) * (16 * LDV);
#pragma unroll
                for (int i = 0; i < 2; i++) ldsm4(afr[nxt][i], aB + i * 16 * LDE + ao);
#pragma unroll
                for (int j = 0; j < 4; j++) ldsm4t(bfr[nxt][j], bB + j * 32 + bo);
            }
#pragma unroll
            for (int i = 0; i < 2; i++)
#pragma unroll
                for (int j = 0; j < 4; j++) {
                    mma16816(d[i][2 * j],     afr[cur][i], &bfr[cur][j][0]);
                    mma16816(d[i][2 * j + 1], afr[cur][i], &bfr[cur][j][2]);
                }
        }
        __syncthreads();

        if (c < 6) {
            const uint32_t abuf = sb + buf * 18432;
            const uint32_t bbuf = sb + 36864 + buf * 17408;
            const int kk = (c + 2) * 64;
#pragma unroll
            for (int q = 0; q < 4; q++)
                cpa16(abuf + (uint32_t)(ar * 144 + (ac * 4 + q) * 16),
                      Eblk + (size_t)ar * 1024 + (size_t)kk * 2 + (ac * 4 + q) * 16);
#pragma unroll
            for (int q = 0; q < 4; q++)
                cpa16(bbuf + (uint32_t)(br * 272 + (bc * 4 + q) * 16),
                      Vblk + (size_t)(kk + br) * 1024 + (bc * 4 + q) * 16);
            CP_COMMIT();
        }
    }

    float* Ob = O + ((size_t)batch * SD + it * 128) * SD + jt * 128;
#pragma unroll
    for (int i = 0; i < 2; i++)
#pragma unroll
        for (int j = 0; j < 8; j++) {
            const int row = R + 16 * i + (lane >> 2);
            const int col = C + 8 * j + (lane & 3) * 2;
            *(float2*)(Ob + (size_t)row * SD + col) = make_float2(d[i][j][0], d[i][j][1]);
            *(float2*)(Ob + (size_t)(row + 8) * SD + col) = make_float2(d[i][j][2], d[i][j][3]);
        }
}

// ---------------------------------------------------------------------------
extern "C" void kernel_launch(void* const* d_in, const int* in_sizes, int n_in,
                              void* d_out, int out_size)
{
    (void)in_sizes; (void)n_in; (void)out_size;
    const float* Q = (const float*)d_in[1];
    const float* K = (const float*)d_in[2];
    const float* V = (const float*)d_in[3];
    float* out = (float*)d_out;

    cudaFuncSetAttribute(k1_qk, cudaFuncAttributeMaxDynamicSharedMemorySize, K1_SMEM);
    cudaFuncSetAttribute(k2_pv, cudaFuncAttributeMaxDynamicSharedMemorySize, K2_SMEM);

    const int nchunk = (int)((size_t)NB * SD * SD / 8);
    dim3 g(16, NB);
    k1_qk<<<g, 256, K1_SMEM>>>(Q, K);
    k_zred<<<NB, 512>>>();
    kvs<<<nchunk / 256, 256>>>(V);
    k2_pv<<<g, 256, K2_SMEM>>>(out);
}